// round 15
// baseline (speedup 1.0000x reference)
#include <cuda_runtime.h>
#include <cuda_fp16.h>
#include <cstdint>

// GridSample1d: N=64, C=64, L_in=4096, L_out=8192, fp32 in/out,
// align_corners=True, padding=border.
//
// R15: CG=2 paired-tap fp16 layout, one-tile blocks.
//  - position i stores 8B = {h2(c0,c1)@i, h2(c0,c1)@i+1}: ONE LDS.64 per
//    (sample, 2 channels) fetches BOTH bilinear taps; no i1/min math.
//  - 32KB buffer -> 6 blocks/SM (48 warps, ~75% occ, 2x R14)
//  - 2048 single-tile blocks: HW work-stealing gives fine-grained balance
//    (tail ~ 1 tile-slice); cross-block desync overlaps reads with writes.

#define N_B     64
#define C_TOT   64
#define L_IN    4096
#define L_OUT   8192
#define CG      2
#define TILES   2048                // 64 n * 32 channel-pairs
#define THREADS 256
#define VEC     4
#define GITERS  (L_OUT / (THREADS * VEC))   // 8

__device__ __forceinline__ uint32_t swz(uint32_t o) {
    return o ^ ((o >> 3) & 0x70);
}
__device__ __forceinline__ uint32_t packh2(float a, float b) {
    __half2 h = __floats2half2_rn(a, b);
    return *reinterpret_cast<uint32_t*>(&h);
}

__global__ __launch_bounds__(THREADS)
void gs1d_kernel(const float* __restrict__ inp,
                 const float* __restrict__ grid,
                 float* __restrict__ out)
{
    extern __shared__ char s_raw[];   // 4096 x 8B paired-tap fp16, swizzled

    const int tid = threadIdx.x;
    const int t   = blockIdx.x;           // tile id
    const int n   = t >> 5;
    const int c0  = (t & 31) * CG;
    const float scale = 0.5f * (float)(L_IN - 1);

    // ---- stage tile: 2 rows fp32 -> paired-tap fp16, swizzled ----
    {
        const float* r0 = inp + ((size_t)n * C_TOT + c0) * L_IN;
        const float* r1 = r0 + L_IN;
        #pragma unroll
        for (int q = 0; q < 4; ++q) {
            const int i0 = tid * 4 + q * 1024;
            const int i4 = min(i0 + 4, L_IN - 1);
            const float4 a0 = __ldcs(reinterpret_cast<const float4*>(r0 + i0));
            const float4 a1 = __ldcs(reinterpret_cast<const float4*>(r1 + i0));
            const float  b0 = __ldcs(r0 + i4);
            const float  b1 = __ldcs(r1 + i4);
            const float v0[5] = {a0.x, a0.y, a0.z, a0.w, b0};
            const float v1[5] = {a1.x, a1.y, a1.z, a1.w, b1};
            #pragma unroll
            for (int k = 0; k < 4; ++k) {
                uint2 v;
                v.x = packh2(v0[k],     v1[k]);      // tap i
                v.y = packh2(v0[k + 1], v1[k + 1]);  // tap i+1
                *reinterpret_cast<uint2*>(s_raw + swz((uint32_t)(i0 + k) * 8u)) = v;
            }
        }
    }
    __syncthreads();

    const float* grow  = grid + (size_t)n * L_OUT;
    float*       obase = out  + ((size_t)n * C_TOT + c0) * L_OUT;

    #pragma unroll
    for (int it = 0; it < GITERS; ++it) {
        const int l0 = it * (THREADS * VEC) + tid * VEC;
        const float4 g = __ldg(reinterpret_cast<const float4*>(grow + l0));
        const float xs[VEC] = {g.x, g.y, g.z, g.w};
        float r0[VEC], r1[VEC];

        #pragma unroll
        for (int j = 0; j < VEC; ++j) {
            float x = (xs[j] + 1.0f) * scale;               // align_corners
            x = fminf(fmaxf(x, 0.0f), (float)(L_IN - 1));   // border clamp
            float xf = floorf(x);
            int   i0 = (int)xf;
            float w1 = x - xf;
            float w0 = 1.0f - w1;

            // ONE LDS.64: both taps x 2 channels
            const uint2 p = *reinterpret_cast<const uint2*>(
                s_raw + swz((uint32_t)i0 * 8u));
            float2 v0 = __half22float2(*reinterpret_cast<const __half2*>(&p.x));
            float2 v1 = __half22float2(*reinterpret_cast<const __half2*>(&p.y));

            r0[j] = w0 * v0.x + w1 * v1.x;
            r1[j] = w0 * v0.y + w1 * v1.y;
        }

        __stcs(reinterpret_cast<float4*>(obase + l0),
               make_float4(r0[0], r0[1], r0[2], r0[3]));
        __stcs(reinterpret_cast<float4*>(obase + L_OUT + l0),
               make_float4(r1[0], r1[1], r1[2], r1[3]));
    }
}

extern "C" void kernel_launch(void* const* d_in, const int* in_sizes, int n_in,
                              void* d_out, int out_size)
{
    const float* inp  = (const float*)d_in[0];  // [64, 64, 4096]
    const float* grid = (const float*)d_in[1];  // [64, 8192]
    float*       out  = (float*)d_out;          // [64, 64, 8192]

    const int smem_bytes = L_IN * 8;            // 32 KB
    cudaFuncSetAttribute(gs1d_kernel,
                         cudaFuncAttributeMaxDynamicSharedMemorySize,
                         smem_bytes);

    gs1d_kernel<<<TILES, THREADS, smem_bytes>>>(inp, grid, out);
}

// round 16
// speedup vs baseline: 1.2187x; 1.2187x over previous
#include <cuda_runtime.h>
#include <cuda_fp16.h>
#include <cstdint>

// GridSample1d: N=64, C=64, L_in=4096, L_out=8192, fp32 in/out,
// align_corners=True, padding=border.
//
// R16: R14 base (CG=4 fp16-interleaved swizzled gather, 256 thr, 444 blocks
// 3/SM, 2x32KB double buffer, VEC=4/STG.128, intra-block pipeline) with a
// finer tail: the last 136 tiles are split 3-way by l_out over blocks
// 0..407 (3/3/2 iterations each) instead of 2-way over 272 blocks.
// Tail logic stays in the same rolled loop body (R12 lesson: unrolled
// phase bodies -> regs>80 -> 2 blocks/SM).

#define N_B     64
#define C_TOT   64
#define L_IN    4096
#define L_OUT   8192
#define CG      4
#define TILES   1024
#define THREADS 256
#define BLOCKS  444
#define BUF_B   (L_IN * 8)          // 32 KB per buffer (uint2 per position)
#define VEC     4

__device__ __forceinline__ uint32_t swz(uint32_t o) {
    return o ^ ((o >> 3) & 0x70);
}
__device__ __forceinline__ uint32_t packh2(float a, float b) {
    __half2 h = __floats2half2_rn(a, b);
    return *reinterpret_cast<uint32_t*>(&h);
}

__device__ __forceinline__ const float* tile_base(const float* inp, int t) {
    const int n = t >> 4, c0 = (t & 15) * CG;
    return inp + ((size_t)n * C_TOT + c0) * L_IN;
}

__device__ __forceinline__ void ldg_chunk(const float* ibase, int i0, float4 a[CG]) {
    #pragma unroll
    for (int c = 0; c < CG; ++c)
        a[c] = __ldcs(reinterpret_cast<const float4*>(ibase + (size_t)c * L_IN + i0));
}
__device__ __forceinline__ void sts_chunk(char* buf, int i0, const float4 a[CG]) {
    #pragma unroll
    for (int k = 0; k < 4; ++k) {
        uint2 v;
        v.x = packh2(((const float*)&a[0])[k], ((const float*)&a[1])[k]);
        v.y = packh2(((const float*)&a[2])[k], ((const float*)&a[3])[k]);
        *reinterpret_cast<uint2*>(buf + swz((uint32_t)(i0 + k) * 8u)) = v;
    }
}

__device__ __forceinline__ void gather_iter_at(int l0, const char* cur,
                                               const float* grow, float* obase,
                                               float scale) {
    const float4 g = __ldg(reinterpret_cast<const float4*>(grow + l0));
    const float xs[VEC] = {g.x, g.y, g.z, g.w};
    float r[CG][VEC];

    #pragma unroll
    for (int j = 0; j < VEC; ++j) {
        float x = (xs[j] + 1.0f) * scale;               // align_corners
        x = fminf(fmaxf(x, 0.0f), (float)(L_IN - 1));   // border clamp
        float xf = floorf(x);
        int   i0 = (int)xf;
        float w1 = x - xf;
        float w0 = 1.0f - w1;
        int   i1 = min(i0 + 1, L_IN - 1);

        const uint2 p0 = *reinterpret_cast<const uint2*>(cur + swz((uint32_t)i0 * 8u));
        const uint2 p1 = *reinterpret_cast<const uint2*>(cur + swz((uint32_t)i1 * 8u));

        float2 v0a = __half22float2(*reinterpret_cast<const __half2*>(&p0.x));
        float2 v0b = __half22float2(*reinterpret_cast<const __half2*>(&p0.y));
        float2 v1a = __half22float2(*reinterpret_cast<const __half2*>(&p1.x));
        float2 v1b = __half22float2(*reinterpret_cast<const __half2*>(&p1.y));

        r[0][j] = w0 * v0a.x + w1 * v1a.x;
        r[1][j] = w0 * v0a.y + w1 * v1a.y;
        r[2][j] = w0 * v0b.x + w1 * v1b.x;
        r[3][j] = w0 * v0b.y + w1 * v1b.y;
    }

    #pragma unroll
    for (int c = 0; c < CG; ++c) {
        float4 o = make_float4(r[c][0], r[c][1], r[c][2], r[c][3]);
        __stcs(reinterpret_cast<float4*>(obase + (size_t)c * L_OUT + l0), o);
    }
}

__global__ __launch_bounds__(THREADS, 3)
void gs1d_kernel(const float* __restrict__ inp,
                 const float* __restrict__ grid,
                 float* __restrict__ out)
{
    extern __shared__ char s_raw[];   // 2 x 32 KB, swizzled fp16-interleaved

    const int tid = threadIdx.x;
    const int b   = blockIdx.x;
    const float scale = 0.5f * (float)(L_IN - 1);
    const int iq0 = tid * 4;          // staging chunks at iq0 + q*1024

    // tail assignment: 136 tiles x 3 segments over blocks 0..407
    const bool hasTail = (b < 408);
    const int  bd3     = b / 3;
    const int  segB    = b - 3 * bd3;
    const int  tTail   = 888 + bd3;
    const int  loTail  = segB * 3072;              // 0 / 3072 / 6144
    const int  itTail  = (segB == 2) ? 2 : 3;      // 3+3+2 iters of 1024
    const int  nItems  = hasTail ? 3 : 2;

    // ---- prologue: stage tile b into buf 0 ----
    {
        const float* ibase = tile_base(inp, b);
        float4 a[CG];
        #pragma unroll
        for (int q = 0; q < 4; ++q) {
            ldg_chunk(ibase, iq0 + q * 1024, a);
            sts_chunk(s_raw, iq0 + q * 1024, a);
        }
    }
    __syncthreads();

    for (int k = 0; k < nItems; ++k) {
        char* cur = s_raw + (k & 1) * BUF_B;
        char* nxt = s_raw + ((k + 1) & 1) * BUF_B;

        const int t  = (k < 2) ? (b + k * 444) : tTail;
        const int n  = t >> 4, c0 = (t & 15) * CG;
        const float* grow  = grid + (size_t)n * L_OUT;
        float*       obase = out  + ((size_t)n * C_TOT + c0) * L_OUT;

        if (k < 2) {
            const bool has_next = (k + 1 < nItems);
            const float* nbase  = inp;
            if (has_next) {
                const int tn = (k == 0) ? (b + 444) : tTail;
                nbase = tile_base(inp, tn);
            }

            float4 a[CG];
            if (has_next) ldg_chunk(nbase, iq0, a);
            gather_iter_at(0 * 1024 + tid * VEC, cur, grow, obase, scale);
            if (has_next) { sts_chunk(nxt, iq0, a); ldg_chunk(nbase, iq0 + 1024, a); }
            gather_iter_at(1 * 1024 + tid * VEC, cur, grow, obase, scale);
            if (has_next) { sts_chunk(nxt, iq0 + 1024, a); ldg_chunk(nbase, iq0 + 2048, a); }
            gather_iter_at(2 * 1024 + tid * VEC, cur, grow, obase, scale);
            if (has_next) { sts_chunk(nxt, iq0 + 2048, a); ldg_chunk(nbase, iq0 + 3072, a); }
            gather_iter_at(3 * 1024 + tid * VEC, cur, grow, obase, scale);
            if (has_next) sts_chunk(nxt, iq0 + 3072, a);
            gather_iter_at(4 * 1024 + tid * VEC, cur, grow, obase, scale);
            gather_iter_at(5 * 1024 + tid * VEC, cur, grow, obase, scale);
            gather_iter_at(6 * 1024 + tid * VEC, cur, grow, obase, scale);
            gather_iter_at(7 * 1024 + tid * VEC, cur, grow, obase, scale);
            __syncthreads();
        } else {
            // tail segment: rolled loop (keeps register count down)
            for (int it = 0; it < itTail; ++it)
                gather_iter_at(loTail + it * 1024 + tid * VEC, cur, grow, obase, scale);
        }
    }
}

extern "C" void kernel_launch(void* const* d_in, const int* in_sizes, int n_in,
                              void* d_out, int out_size)
{
    const float* inp  = (const float*)d_in[0];  // [64, 64, 4096]
    const float* grid = (const float*)d_in[1];  // [64, 8192]
    float*       out  = (float*)d_out;          // [64, 64, 8192]

    const int smem_bytes = 2 * BUF_B;           // 64 KB
    cudaFuncSetAttribute(gs1d_kernel,
                         cudaFuncAttributeMaxDynamicSharedMemorySize,
                         smem_bytes);

    gs1d_kernel<<<BLOCKS, THREADS, smem_bytes>>>(inp, grid, out);
}

// round 17
// speedup vs baseline: 1.2260x; 1.0060x over previous
#include <cuda_runtime.h>
#include <cuda_fp16.h>
#include <cstdint>

// GridSample1d: N=64, C=64, L_in=4096, L_out=8192, fp32 in/out,
// align_corners=True, padding=border.
//
// R17: R14's pipeline at 32 warps/SM. THREADS=512, launch_bounds(512,2)
// -> 2 blocks/SM, 64 regs/thread (exact RF fill, no spill), 2x32KB double
// buffer, CG=4 fp16-interleaved swizzled gather, VEC=4/STG.128.
// Staging in 2-channel half-chunks keeps only 8 regs live across each
// gather iteration (R8's spill fix). 296 persistent blocks: 3 full rounds
// + 136 tail tiles split 2-way over 272 blocks.

#define N_B     64
#define C_TOT   64
#define L_IN    4096
#define L_OUT   8192
#define CG      4
#define TILES   1024
#define THREADS 512
#define BLOCKS  296                 // 2 * 148 SMs
#define BUF_B   (L_IN * 8)          // 32 KB per buffer (uint2 per position)
#define VEC     4
#define GITERS  4                   // 8192 / (512*4)

__device__ __forceinline__ uint32_t swz(uint32_t o) {
    return o ^ ((o >> 3) & 0x70);
}
__device__ __forceinline__ uint32_t packh2(float a, float b) {
    __half2 h = __floats2half2_rn(a, b);
    return *reinterpret_cast<uint32_t*>(&h);
}

__device__ __forceinline__ const float* tile_base(const float* inp, int t) {
    const int n = t >> 4, c0 = (t & 15) * CG;
    return inp + ((size_t)n * C_TOT + c0) * L_IN;
}

// 2-channel staging half-chunk: 4 positions x 2 channels = 8 regs
__device__ __forceinline__ void ldg2(const float* ibase, int cpair, int i0,
                                     float4 a[2]) {
    a[0] = __ldcs(reinterpret_cast<const float4*>(ibase + (size_t)(2*cpair)   * L_IN + i0));
    a[1] = __ldcs(reinterpret_cast<const float4*>(ibase + (size_t)(2*cpair+1) * L_IN + i0));
}
__device__ __forceinline__ void sts2(char* buf, int cpair, int i0,
                                     const float4 a[2]) {
    #pragma unroll
    for (int k = 0; k < 4; ++k) {
        uint32_t w = packh2(((const float*)&a[0])[k], ((const float*)&a[1])[k]);
        *reinterpret_cast<uint32_t*>(
            buf + swz((uint32_t)(i0 + k) * 8u) + cpair * 4) = w;
    }
}

__device__ __forceinline__ void gather_iter_at(int l0, const char* cur,
                                               const float* grow, float* obase,
                                               float scale) {
    const float4 g = __ldg(reinterpret_cast<const float4*>(grow + l0));
    const float xs[VEC] = {g.x, g.y, g.z, g.w};
    float r[CG][VEC];

    #pragma unroll
    for (int j = 0; j < VEC; ++j) {
        float x = (xs[j] + 1.0f) * scale;               // align_corners
        x = fminf(fmaxf(x, 0.0f), (float)(L_IN - 1));   // border clamp
        float xf = floorf(x);
        int   i0 = (int)xf;
        float w1 = x - xf;
        float w0 = 1.0f - w1;
        int   i1 = min(i0 + 1, L_IN - 1);

        const uint2 p0 = *reinterpret_cast<const uint2*>(cur + swz((uint32_t)i0 * 8u));
        const uint2 p1 = *reinterpret_cast<const uint2*>(cur + swz((uint32_t)i1 * 8u));

        float2 v0a = __half22float2(*reinterpret_cast<const __half2*>(&p0.x));
        float2 v0b = __half22float2(*reinterpret_cast<const __half2*>(&p0.y));
        float2 v1a = __half22float2(*reinterpret_cast<const __half2*>(&p1.x));
        float2 v1b = __half22float2(*reinterpret_cast<const __half2*>(&p1.y));

        r[0][j] = w0 * v0a.x + w1 * v1a.x;
        r[1][j] = w0 * v0a.y + w1 * v1a.y;
        r[2][j] = w0 * v0b.x + w1 * v1b.x;
        r[3][j] = w0 * v0b.y + w1 * v1b.y;
    }

    #pragma unroll
    for (int c = 0; c < CG; ++c) {
        float4 o = make_float4(r[c][0], r[c][1], r[c][2], r[c][3]);
        __stcs(reinterpret_cast<float4*>(obase + (size_t)c * L_OUT + l0), o);
    }
}

__global__ __launch_bounds__(THREADS, 2)
void gs1d_kernel(const float* __restrict__ inp,
                 const float* __restrict__ grid,
                 float* __restrict__ out)
{
    extern __shared__ char s_raw[];   // 2 x 32 KB, swizzled fp16-interleaved

    const int tid = threadIdx.x;
    const int b   = blockIdx.x;
    const float scale = 0.5f * (float)(L_IN - 1);
    const int iq0 = tid * 4;          // position chunks at iq0 and iq0+2048

    // tail: 136 tiles x 2 l_out halves over blocks 0..271
    const bool hasTail = (b < 272);
    const int  tTail   = 888 + (b >> 1);
    const int  loTail  = (b & 1) * 4096;
    const int  nItems  = hasTail ? 4 : 3;

    // ---- prologue: stage tile b into buf 0 ----
    {
        const float* ibase = tile_base(inp, b);
        float4 a[2];
        #pragma unroll
        for (int q = 0; q < 2; ++q) {
            #pragma unroll
            for (int cp = 0; cp < 2; ++cp) {
                ldg2(ibase, cp, iq0 + q * 2048, a);
                sts2(s_raw, cp, iq0 + q * 2048, a);
            }
        }
    }
    __syncthreads();

    for (int k = 0; k < nItems; ++k) {
        char* cur = s_raw + (k & 1) * BUF_B;
        char* nxt = s_raw + ((k + 1) & 1) * BUF_B;

        const int t  = (k < 3) ? (b + k * BLOCKS) : tTail;
        const int n  = t >> 4, c0 = (t & 15) * CG;
        const float* grow  = grid + (size_t)n * L_OUT;
        float*       obase = out  + ((size_t)n * C_TOT + c0) * L_OUT;

        if (k < 3) {
            const bool has_next = (k + 1 < nItems);
            const float* nbase  = inp;
            if (has_next) {
                const int tn = (k < 2) ? (b + (k + 1) * BLOCKS) : tTail;
                nbase = tile_base(inp, tn);
            }

            float4 a[2];
            if (has_next) ldg2(nbase, 0, iq0, a);
            gather_iter_at(0 * 2048 + tid * VEC, cur, grow, obase, scale);
            if (has_next) { sts2(nxt, 0, iq0, a); ldg2(nbase, 1, iq0, a); }
            gather_iter_at(1 * 2048 + tid * VEC, cur, grow, obase, scale);
            if (has_next) { sts2(nxt, 1, iq0, a); ldg2(nbase, 0, iq0 + 2048, a); }
            gather_iter_at(2 * 2048 + tid * VEC, cur, grow, obase, scale);
            if (has_next) { sts2(nxt, 0, iq0 + 2048, a); ldg2(nbase, 1, iq0 + 2048, a); }
            gather_iter_at(3 * 2048 + tid * VEC, cur, grow, obase, scale);
            if (has_next) sts2(nxt, 1, iq0 + 2048, a);
            __syncthreads();
        } else {
            // tail half: 2 gather iterations, nothing to stage
            gather_iter_at(loTail + 0 * 2048 + tid * VEC, cur, grow, obase, scale);
            gather_iter_at(loTail + 1 * 2048 + tid * VEC, cur, grow, obase, scale);
        }
    }
}

extern "C" void kernel_launch(void* const* d_in, const int* in_sizes, int n_in,
                              void* d_out, int out_size)
{
    const float* inp  = (const float*)d_in[0];  // [64, 64, 4096]
    const float* grid = (const float*)d_in[1];  // [64, 8192]
    float*       out  = (float*)d_out;          // [64, 64, 8192]

    const int smem_bytes = 2 * BUF_B;           // 64 KB
    cudaFuncSetAttribute(gs1d_kernel,
                         cudaFuncAttributeMaxDynamicSharedMemorySize,
                         smem_bytes);

    gs1d_kernel<<<BLOCKS, THREADS, smem_bytes>>>(inp, grid, out);
}